// round 4
// baseline (speedup 1.0000x reference)
#include <cuda_runtime.h>

// CNODExtmod: controlled neural ODE, persistent per-CTA time loop.
// R4: packed fp32x2 (FFMA2) column-pair GEMV for L1/L2, multi-accumulator ILP.

#define NCC      32
#define NC1      33
#define HID      128
#define TT       64
#define NSUB     4
#define ROWS     32
#define NTHREADS 256
#define DTC      0.01f
#define CNS      36
#define XS       128

#define O_Y2 262144
#define O_T  524288
#define O_H  524352

typedef unsigned long long u64;

__device__ __forceinline__ u64 pk1(float x) {
    u64 r; asm("mov.b64 %0,{%1,%1};" : "=l"(r) : "f"(x)); return r;
}
__device__ __forceinline__ u64 pk2(float a, float b) {
    u64 r; asm("mov.b64 %0,{%1,%2};" : "=l"(r) : "f"(a), "f"(b)); return r;
}
__device__ __forceinline__ void fma2(u64& d, u64 a, u64 b) {
    asm("fma.rn.f32x2 %0,%1,%2,%0;" : "+l"(d) : "l"(a), "l"(b));
}
__device__ __forceinline__ u64 add2(u64 a, u64 b) {
    u64 r; asm("add.rn.f32x2 %0,%1,%2;" : "=l"(r) : "l"(a), "l"(b)); return r;
}
__device__ __forceinline__ void upk(u64 v, float& a, float& b) {
    asm("mov.b64 {%0,%1},%2;" : "=f"(a), "=f"(b) : "l"(v));
}

#define FMA4(acc, xv, wt, bofs) {                        \
    acc = fmaf((wt)[(bofs)+0], (xv).x, acc);             \
    acc = fmaf((wt)[(bofs)+1], (xv).y, acc);             \
    acc = fmaf((wt)[(bofs)+2], (xv).z, acc);             \
    acc = fmaf((wt)[(bofs)+3], (xv).w, acc); }

__global__ void __launch_bounds__(NTHREADS, 1)
cnode_kernel(const float* __restrict__ times, const float* __restrict__ Y,
             const float* __restrict__ mask,  const float* __restrict__ A,
             const float* __restrict__ Bvec,
             const float* __restrict__ W1, const float* __restrict__ b1,
             const float* __restrict__ W2, const float* __restrict__ b2,
             const float* __restrict__ W3, const float* __restrict__ b3,
             float* __restrict__ out)
{
    __shared__ __align__(16) float CN0[ROWS * CNS];
    __shared__ __align__(16) float CN1[ROWS * CNS];
    __shared__ __align__(16) float X1 [ROWS * XS];
    __shared__ __align__(16) float X2 [ROWS * XS];
    __shared__ __align__(16) float DC1[ROWS * NCC];
    __shared__ float ysh[ROWS];
    __shared__ float msh[ROWS];

    const int tid = threadIdx.x;
    const int b0  = blockIdx.x * ROWS;

    // role decompositions
    const int jp = tid >> 2;         // 0..63 : output col-PAIR for L1/L2
    const int s4 = tid & 3;          // K-quarter for L1/L2
    const int j0 = 2 * jp, j1 = j0 + 1;
    const int j3 = tid >> 3;         // 0..31 : output col for L3 / row for o32
    const int s3 = tid & 7;          // K-eighth for L3/o32
    const int ia = tid & 31;         // 0..31 : output col for A pass
    const int rg = tid >> 5;         // warp id : row group for A pass

    // ---- packed weights (once) ----
    // L1: cols (j0,j1), K slice s4*8..+8, plus k=32 folded onto s4==0
    u64 w1p[8];
    #pragma unroll
    for (int i = 0; i < 8; i++)
        w1p[i] = pk2(W1[j0 * NC1 + s4 * 8 + i], W1[j1 * NC1 + s4 * 8 + i]);
    const u64 w1x = (s4 == 0) ? pk2(W1[j0 * NC1 + 32], W1[j1 * NC1 + 32]) : 0ull;
    const float b10 = b1[j0], b11 = b1[j1];

    // L2: cols (j0,j1), K slice s4*32..+32
    u64 w2p[32];
    #pragma unroll
    for (int i = 0; i < 32; i++)
        w2p[i] = pk2(W2[j0 * HID + s4 * 32 + i], W2[j1 * HID + s4 * 32 + i]);
    const float b20 = b2[j0], b21 = b2[j1];

    // L3 (scalar, unchanged): thread s3 owns k = s3*4 + 32*m + q
    float w3r[16];
    #pragma unroll
    for (int m = 0; m < 4; m++)
        #pragma unroll
        for (int q = 0; q < 4; q++)
            w3r[m * 4 + q] = W3[j3 * HID + s3 * 4 + m * 32 + q];
    const float b3j = b3[j3];

    float w32r[16];
    #pragma unroll
    for (int m = 0; m < 4; m++)
        #pragma unroll
        for (int q = 0; q < 4; q++)
            w32r[m * 4 + q] = W3[NCC * HID + s3 * 4 + m * 32 + q];
    const float b3_32 = b3[NCC];

    float wAr[32];
    #pragma unroll
    for (int k = 0; k < 32; k++) wAr[k] = A[ia * NCC + k];
    const float Bi = Bvec[ia];

    // ---- init ----
    for (int idx = tid; idx < ROWS * CNS; idx += NTHREADS) {
        CN0[idx] = 0.0f; CN1[idx] = 0.0f;
    }
    if (blockIdx.x == 0 && tid < TT) out[O_T + tid] = times[tid];

    float y_t = 0.0f, m_t = 0.0f;
    if (tid < ROWS) {
        y_t = Y[(b0 + tid) * TT];
        m_t = mask[(b0 + tid) * TT];
    }
    __syncthreads();

    for (int t = 0; t < TT; t++) {
        for (int sub = 0; sub < NSUB; sub++) {
            // ---------- L1: X1 = relu(W1 @ cn1 + b1), packed col-pairs ----------
            #pragma unroll 2
            for (int r = 0; r < ROWS; r++) {
                const float* cr = CN1 + r * CNS + s4 * 8;
                u64 a0 = 0ull, a1 = 0ull;
                float4 xv = *(const float4*)(cr);
                fma2(a0, w1p[0], pk1(xv.x));
                fma2(a1, w1p[1], pk1(xv.y));
                fma2(a0, w1p[2], pk1(xv.z));
                fma2(a1, w1p[3], pk1(xv.w));
                xv = *(const float4*)(cr + 4);
                fma2(a0, w1p[4], pk1(xv.x));
                fma2(a1, w1p[5], pk1(xv.y));
                fma2(a0, w1p[6], pk1(xv.z));
                fma2(a1, w1p[7], pk1(xv.w));
                fma2(a0, w1x, pk1(CN1[r * CNS + 32]));
                float f0, f1; upk(add2(a0, a1), f0, f1);
                f0 += __shfl_xor_sync(0xffffffffu, f0, 1);
                f0 += __shfl_xor_sync(0xffffffffu, f0, 2);
                f1 += __shfl_xor_sync(0xffffffffu, f1, 1);
                f1 += __shfl_xor_sync(0xffffffffu, f1, 2);
                if (s4 == 0) {
                    float2 o;
                    o.x = fmaxf(f0 + b10, 0.0f);
                    o.y = fmaxf(f1 + b11, 0.0f);
                    *(float2*)(X1 + r * XS + j0) = o;
                }
            }
            __syncthreads();

            // ---------- L2: X2 = relu(W2 @ X1 + b2), packed col-pairs ----------
            #pragma unroll 2
            for (int r = 0; r < ROWS; r++) {
                const float* xr = X1 + r * XS + s4 * 32;
                u64 a0 = 0ull, a1 = 0ull;
                #pragma unroll
                for (int v = 0; v < 8; v++) {
                    float4 xv = *(const float4*)(xr + v * 4);
                    fma2(a0, w2p[v * 4 + 0], pk1(xv.x));
                    fma2(a1, w2p[v * 4 + 1], pk1(xv.y));
                    fma2(a0, w2p[v * 4 + 2], pk1(xv.z));
                    fma2(a1, w2p[v * 4 + 3], pk1(xv.w));
                }
                float f0, f1; upk(add2(a0, a1), f0, f1);
                f0 += __shfl_xor_sync(0xffffffffu, f0, 1);
                f0 += __shfl_xor_sync(0xffffffffu, f0, 2);
                f1 += __shfl_xor_sync(0xffffffffu, f1, 1);
                f1 += __shfl_xor_sync(0xffffffffu, f1, 2);
                if (s4 == 0) {
                    float2 o;
                    o.x = fmaxf(f0 + b20, 0.0f);
                    o.y = fmaxf(f1 + b21, 0.0f);
                    *(float2*)(X2 + r * XS + j0) = o;
                }
            }
            __syncthreads();

            // ---------- phase 3: derivative reads (no state writes) ----------
            float dcn0[4];
            #pragma unroll
            for (int q = 0; q < 4; q++) {
                const int r = rg * 4 + q;
                const float* cr = CN0 + r * CNS;
                float acc = 0.0f;
                #pragma unroll
                for (int v = 0; v < 8; v++) {
                    float4 xv = *(const float4*)(cr + v * 4);
                    FMA4(acc, xv, wAr, v * 4);
                }
                dcn0[q] = fmaf(Bi, CN1[r * CNS], acc);
            }

            float o32;
            {
                const float* xr = X2 + j3 * XS;
                float acc = 0.0f;
                #pragma unroll
                for (int m = 0; m < 4; m++) {
                    float4 xv = *(const float4*)(xr + s3 * 4 + m * 32);
                    FMA4(acc, xv, w32r, m * 4);
                }
                acc += __shfl_xor_sync(0xffffffffu, acc, 1);
                acc += __shfl_xor_sync(0xffffffffu, acc, 2);
                acc += __shfl_xor_sync(0xffffffffu, acc, 4);
                o32 = acc + b3_32;
            }

            #pragma unroll 2
            for (int r = 0; r < ROWS; r++) {
                const float* xr = X2 + r * XS;
                float acc = 0.0f;
                #pragma unroll
                for (int m = 0; m < 4; m++) {
                    float4 xv = *(const float4*)(xr + s3 * 4 + m * 32);
                    FMA4(acc, xv, w3r, m * 4);
                }
                acc += __shfl_xor_sync(0xffffffffu, acc, 1);
                acc += __shfl_xor_sync(0xffffffffu, acc, 2);
                acc += __shfl_xor_sync(0xffffffffu, acc, 4);
                if (s3 == 0) DC1[r * NCC + j3] = acc + b3j;
            }
            __syncthreads();

            // ---------- phase 4: Euler update ----------
            #pragma unroll
            for (int q = 0; q < 4; q++) {
                const int r = rg * 4 + q;
                CN0[r * CNS + ia] += DTC * dcn0[q];
            }
            #pragma unroll
            for (int u = 0; u < 4; u++) {
                const int idx = tid + u * NTHREADS;
                const int r = idx >> 5, jj = idx & 31;
                CN1[r * CNS + jj] += DTC * DC1[idx];
            }
            if (s3 == 0) CN1[j3 * CNS + 32] += DTC * o32;
            __syncthreads();
        }

        // ---------- observation step ----------
        if (tid < ROWS) {
            const float yp = CN1[tid * CNS];
            out[(b0 + tid) * TT + t]        = yp;
            out[O_Y2 + (b0 + tid) * TT + t] = yp;
            ysh[tid] = y_t;
            msh[tid] = m_t;
        }
        __syncthreads();

        for (int idx = tid; idx < ROWS * NC1; idx += NTHREADS) {
            const int r  = idx / NC1;
            const int jj = idx - r * NC1;
            if (msh[r] != 0.0f) {
                CN1[r * CNS + jj] = (jj == 0) ? ysh[r] : CN0[r * CNS + jj - 1];
            }
        }
        if (tid < ROWS && t + 1 < TT) {
            y_t = Y[(b0 + tid) * TT + t + 1];
            m_t = mask[(b0 + tid) * TT + t + 1];
        }
        __syncthreads();
    }

    for (int idx = tid; idx < ROWS * NCC; idx += NTHREADS) {
        const int r = idx >> 5, i = idx & 31;
        out[O_H + (b0 + r) * NCC + i] = CN0[r * CNS + i];
    }
}

extern "C" void kernel_launch(void* const* d_in, const int* in_sizes, int n_in,
                              void* d_out, int out_size)
{
    const float* times = (const float*)d_in[0];
    const float* Y     = (const float*)d_in[1];
    const float* mask  = (const float*)d_in[2];
    const float* A     = (const float*)d_in[3];
    const float* Bvec  = (const float*)d_in[4];
    const float* W1    = (const float*)d_in[5];
    const float* b1    = (const float*)d_in[6];
    const float* W2    = (const float*)d_in[7];
    const float* b2    = (const float*)d_in[8];
    const float* W3    = (const float*)d_in[9];
    const float* b3    = (const float*)d_in[10];
    float* out = (float*)d_out;

    cnode_kernel<<<128, NTHREADS>>>(times, Y, mask, A, Bvec,
                                    W1, b1, W2, b2, W3, b3, out);
}